// round 1
// baseline (speedup 1.0000x reference)
#include <cuda_runtime.h>
#include <cstdint>

#define NB 16
#define NA 128
#define CH 512
#define EF 30
#define KK 1024   // 2*CH

// 4 MB scratch for h1 (device global: allocation-free)
__device__ float g_h1[(size_t)NB * NA * CH];

// ---------------- packed f32x2 helpers (sm_103a FFMA2) ----------------
__device__ __forceinline__ unsigned long long pack2(float lo, float hi) {
    unsigned long long r;
    asm("mov.b64 %0, {%1, %2};" : "=l"(r) : "f"(lo), "f"(hi));
    return r;
}
__device__ __forceinline__ void unpack2(unsigned long long v, float& lo, float& hi) {
    asm("mov.b64 {%0, %1}, %2;" : "=f"(lo), "=f"(hi) : "l"(v));
}
__device__ __forceinline__ void fma2(unsigned long long& d, unsigned long long a,
                                     unsigned long long b) {
    asm("fma.rn.f32x2 %0, %1, %2, %0;" : "+l"(d) : "l"(a), "l"(b));
}

// selu(x) = scale * (x>0 ? x : alpha*(exp(x)-1))
__device__ __forceinline__ float selu_f(float x) {
    const float sc  = 1.0507009873554805f;
    const float sca = 1.7580993408473766f;  // scale*alpha
    float ex  = __expf(x);
    float neg = fmaf(ex, sca, -sca);
    float pos = sc * x;
    return (x > 0.0f) ? pos : neg;
}

// =====================================================================
// Kernel 1: fused edge filter (Linear 30->512 + SELU + edge_mask) and
//           aggregation h1[b,i,c] = sum_j ef[b,i,j,c] * h[b,j,c]
// One CTA per (b,i). 512 threads, one output channel per thread.
// =====================================================================
__global__ void __launch_bounds__(512)
edge_agg_kernel(const float* __restrict__ h,
                const float* __restrict__ e,
                const float* __restrict__ emask,
                const float* __restrict__ fW,
                const float* __restrict__ fb) {
    __shared__ float es[NA * 32];   // 128 rows x 32 cols (30 + 2 zero pad)
    __shared__ float ems[NA];

    const int bi  = blockIdx.x;       // b*NA + i
    const int b   = bi >> 7;
    const int tid = threadIdx.x;      // channel c

    // stage e[b,i,:, :] into padded smem
    const float* ep = e + (size_t)bi * (NA * EF);
    for (int idx = tid; idx < NA * EF; idx += 512) {
        int r = idx / EF;
        int c = idx - r * EF;
        es[r * 32 + c] = ep[idx];
    }
    if (tid < NA * 2) es[(tid >> 1) * 32 + 30 + (tid & 1)] = 0.0f;  // pad cols
    if (tid < NA) ems[tid] = emask[(size_t)bi * NA + tid];

    // filter weights for this channel: 15 packed pairs in registers
    const float* wr = fW + tid * EF;
    unsigned long long w2[15];
#pragma unroll
    for (int k = 0; k < 15; k++) w2[k] = pack2(wr[2 * k], wr[2 * k + 1]);
    const float bias = fb[tid];

    __syncthreads();

    const float* hb = h + (size_t)b * NA * CH + tid;  // h[b][j][c], stride CH
    float acc = 0.0f;

    // prefetch h two iterations ahead
    float hcur  = __ldg(hb);
    float hnext = __ldg(hb + CH);

    const ulonglong2* esr = (const ulonglong2*)es;  // 8 x 16B per row

#pragma unroll 2
    for (int j = 0; j < NA; j++) {
        const ulonglong2* row = esr + j * 8;
        unsigned long long d0 = 0ULL, d1 = 0ULL;
#pragma unroll
        for (int k = 0; k < 8; k++) {
            ulonglong2 v = row[k];
            fma2(d0, v.x, w2[2 * k]);
            if (k < 7) fma2(d1, v.y, w2[2 * k + 1]);  // pair 15 is zero pad
        }
        float l0, h0, l1, h1;
        unpack2(d0, l0, h0);
        unpack2(d1, l1, h1);
        float x = (l0 + h0) + (l1 + h1) + bias;
        float v = selu_f(x) * ems[j];

        acc = fmaf(v, hcur, acc);
        hcur = hnext;
        hnext = (j + 2 < NA) ? __ldg(hb + (size_t)(j + 2) * CH) : 0.0f;
    }

    g_h1[(size_t)bi * CH + tid] = acc;
}

// =====================================================================
// Kernel 2: node MLP.  out[m,n] = selu( z[m,:] . w_W[n,:] + w_b[n] ) * nm[m] + h[m,n]
// z = concat(h, h1) read from the two sources. Tiled GEMM 64x64x32,
// 256 threads, 4x4 outputs per thread, f32x2 accumulators.
// =====================================================================
#define BM 64
#define BN 64
#define BK 32
#define APAD 68   // 16B-aligned padded row stride

__global__ void __launch_bounds__(256)
node_mlp_kernel(const float* __restrict__ h,
                const float* __restrict__ nmask,
                const float* __restrict__ wW,
                const float* __restrict__ wb,
                float* __restrict__ out) {
    __shared__ float As[BK][APAD];
    __shared__ float Bs[BK][APAD];

    const int n0  = blockIdx.x * BN;
    const int m0  = blockIdx.y * BM;
    const int tid = threadIdx.x;
    const int tx  = tid & 15;   // n direction
    const int ty  = tid >> 4;   // m direction

    unsigned long long acc[4][2];
#pragma unroll
    for (int i = 0; i < 4; i++) { acc[i][0] = 0ULL; acc[i][1] = 0ULL; }

    for (int k0 = 0; k0 < KK; k0 += BK) {
        const float* Asrc = (k0 < CH) ? (h + k0) : (g_h1 + (k0 - CH));
        // cooperative loads: 64x32 each, 8 elems per thread
#pragma unroll
        for (int u = 0; u < 8; u++) {
            int idx = tid + u * 256;
            int r = idx >> 5;        // row (m or n)
            int k = idx & 31;
            As[k][r] = Asrc[(size_t)(m0 + r) * CH + k];
            Bs[k][r] = wW[(size_t)(n0 + r) * KK + k0 + k];
        }
        __syncthreads();

#pragma unroll
        for (int k = 0; k < BK; k++) {
            float4 a = *(const float4*)&As[k][ty * 4];
            ulonglong2 bb = *(const ulonglong2*)&Bs[k][tx * 4];
            unsigned long long a0 = pack2(a.x, a.x);
            unsigned long long a1 = pack2(a.y, a.y);
            unsigned long long a2 = pack2(a.z, a.z);
            unsigned long long a3 = pack2(a.w, a.w);
            fma2(acc[0][0], a0, bb.x); fma2(acc[0][1], a0, bb.y);
            fma2(acc[1][0], a1, bb.x); fma2(acc[1][1], a1, bb.y);
            fma2(acc[2][0], a2, bb.x); fma2(acc[2][1], a2, bb.y);
            fma2(acc[3][0], a3, bb.x); fma2(acc[3][1], a3, bb.y);
        }
        __syncthreads();
    }

    // epilogue: bias + selu + node mask + residual
    const float4 bv = *(const float4*)(wb + n0 + tx * 4);
#pragma unroll
    for (int i = 0; i < 4; i++) {
        int m = m0 + ty * 4 + i;
        float nmv = nmask[m];
        float v0, v1, v2, v3;
        unpack2(acc[i][0], v0, v1);
        unpack2(acc[i][1], v2, v3);
        const float4 hres = *(const float4*)(h + (size_t)m * CH + n0 + tx * 4);
        float4 o;
        o.x = selu_f(v0 + bv.x) * nmv + hres.x;
        o.y = selu_f(v1 + bv.y) * nmv + hres.y;
        o.z = selu_f(v2 + bv.z) * nmv + hres.z;
        o.w = selu_f(v3 + bv.w) * nmv + hres.w;
        *(float4*)(out + (size_t)m * CH + n0 + tx * 4) = o;
    }
}

// =====================================================================
extern "C" void kernel_launch(void* const* d_in, const int* in_sizes, int n_in,
                              void* d_out, int out_size) {
    (void)in_sizes; (void)n_in; (void)out_size;
    const float* h     = (const float*)d_in[0];
    const float* e     = (const float*)d_in[1];
    const float* nmask = (const float*)d_in[2];
    const float* emask = (const float*)d_in[3];
    const float* fW    = (const float*)d_in[4];
    const float* fb    = (const float*)d_in[5];
    const float* wW    = (const float*)d_in[6];
    const float* wb    = (const float*)d_in[7];
    float* out = (float*)d_out;

    edge_agg_kernel<<<NB * NA, 512>>>(h, e, emask, fW, fb);
    node_mlp_kernel<<<dim3(CH / BN, (NB * NA) / BM), 256>>>(h, nmask, wW, wb, out);
}

// round 3
// speedup vs baseline: 1.3575x; 1.3575x over previous
#include <cuda_runtime.h>
#include <cuda_bf16.h>
#include <cstdint>

#define NB 16
#define NA 128
#define CH 512
#define EF 30
#define KK 1024   // 2*CH

// 4 MB scratch for h1 (device global: allocation-free)
__device__ float g_h1[(size_t)NB * NA * CH];

// ---------------- packed f32x2 helpers (sm_103a FFMA2) ----------------
__device__ __forceinline__ unsigned long long pack2(float lo, float hi) {
    unsigned long long r;
    asm("mov.b64 %0, {%1, %2};" : "=l"(r) : "f"(lo), "f"(hi));
    return r;
}
__device__ __forceinline__ void unpack2(unsigned long long v, float& lo, float& hi) {
    asm("mov.b64 {%0, %1}, %2;" : "=f"(lo), "=f"(hi) : "l"(v));
}
__device__ __forceinline__ void fma2(unsigned long long& d, unsigned long long a,
                                     unsigned long long b) {
    asm("fma.rn.f32x2 %0, %1, %2, %0;" : "+l"(d) : "l"(a), "l"(b));
}

// selu(x) = scale * (x>0 ? x : alpha*(exp(x)-1))
__device__ __forceinline__ float selu_f(float x) {
    const float sc  = 1.0507009873554805f;
    const float sca = 1.7580993408473766f;  // scale*alpha
    float ex  = __expf(x);
    float neg = fmaf(ex, sca, -sca);
    float pos = sc * x;
    return (x > 0.0f) ? pos : neg;
}

__device__ __forceinline__ uint32_t smem_u32(const void* p) {
    uint32_t a;
    asm("{ .reg .u64 t; cvta.to.shared.u64 t, %1; cvt.u32.u64 %0, t; }" : "=r"(a) : "l"(p));
    return a;
}

// ldmatrix x4 (sm_75+; safe on plain sm_103)
#define LDSM_X4(r, addr) \
    asm volatile("ldmatrix.sync.aligned.m8n8.x4.shared.b16 {%0,%1,%2,%3}, [%4];" \
        : "=r"((r)[0]), "=r"((r)[1]), "=r"((r)[2]), "=r"((r)[3]) : "r"(addr))

// mma m16n8k16 bf16 (sm_80+; safe on plain sm_103)
__device__ __forceinline__ void mma_bf16(float* d, const uint32_t* a,
                                         uint32_t b0, uint32_t b1) {
    asm volatile(
        "mma.sync.aligned.m16n8k16.row.col.f32.bf16.bf16.f32 "
        "{%0,%1,%2,%3}, {%4,%5,%6,%7}, {%8,%9}, {%0,%1,%2,%3};"
        : "+f"(d[0]), "+f"(d[1]), "+f"(d[2]), "+f"(d[3])
        : "r"(a[0]), "r"(a[1]), "r"(a[2]), "r"(a[3]), "r"(b0), "r"(b1));
}

// =====================================================================
// Edge kernel (mma.sync): one CTA per (b,i).
// D[c,j] = fW[c,:].e[b,i,j,:] via bf16-split 3-pass m16n8k16.
// Fused epilogue: h1[bi,c] = sum_j selu(D+fb[c]) * emask[j] * h[b,j,c].
//
// smem rows are 80B (40 bf16): 8 consecutive ldmatrix rows -> 8 distinct
// 16B bank groups => conflict-free.
// Layout: AH[512][80B] | AL[512][80B] | EH[128][80B] | EL[128][80B] | ems[128]f
// =====================================================================
#define ROWB 80
#define OFF_AH 0
#define OFF_AL 40960
#define OFF_EH 81920
#define OFF_EL 92160
#define OFF_EMS 102400
#define EDGE_SMEM 102912

__global__ void __launch_bounds__(512)
edge_mma_kernel(const float* __restrict__ h,
                const float* __restrict__ e,
                const float* __restrict__ emask,
                const float* __restrict__ fW,
                const float* __restrict__ fb) {
    extern __shared__ char smem[];
    const uint32_t sb = smem_u32(smem);
    const int tid = threadIdx.x;
    const int bi  = blockIdx.x;
    const int b   = bi >> 7;
    float* ems = (float*)(smem + OFF_EMS);

    // zero whole staging region (k=30,31 padding must be 0)
    {
        uint4 z = make_uint4(0, 0, 0, 0);
        uint4* p = (uint4*)smem;
        for (int i = tid; i < EDGE_SMEM / 16; i += 512) p[i] = z;
    }
    __syncthreads();

    // A = fW (512 x 30), bf16 hi/lo split
    for (int idx = tid; idx < CH * EF; idx += 512) {
        int r = idx / EF, c = idx - r * EF;
        float v = fW[idx];
        __nv_bfloat16 hi = __float2bfloat16(v);
        __nv_bfloat16 lo = __float2bfloat16(v - __bfloat162float(hi));
        *(__nv_bfloat16*)(smem + OFF_AH + r * ROWB + c * 2) = hi;
        *(__nv_bfloat16*)(smem + OFF_AL + r * ROWB + c * 2) = lo;
    }
    // B = e[b,i,:,:] (128 x 30), bf16 hi/lo split
    const float* ep = e + (size_t)bi * (NA * EF);
    for (int idx = tid; idx < NA * EF; idx += 512) {
        int r = idx / EF, c = idx - r * EF;
        float v = ep[idx];
        __nv_bfloat16 hi = __float2bfloat16(v);
        __nv_bfloat16 lo = __float2bfloat16(v - __bfloat162float(hi));
        *(__nv_bfloat16*)(smem + OFF_EH + r * ROWB + c * 2) = hi;
        *(__nv_bfloat16*)(smem + OFF_EL + r * ROWB + c * 2) = lo;
    }
    if (tid < NA) ems[tid] = emask[(size_t)bi * NA + tid];
    __syncthreads();

    const int w   = tid >> 5;      // 16 warps
    const int l   = tid & 31;
    const int gid = l >> 2;        // 0..7
    const int tig = l & 3;         // 0..3
    const int cbase = w * 32;      // 32 channels per warp

    // ---- A fragment ldmatrix addresses ----
    // lanes 0-15: row = rowbase + (l&15), k-lo; lanes 16-31: same rows, k+8
    const int arow_off = (l & 15);
    const int akk_off  = ((l >> 4) << 3);

    uint32_t AH[2][2][4], AL[2][2][4];   // [m-tile][k-step][4]
#pragma unroll
    for (int mt = 0; mt < 2; mt++)
#pragma unroll
        for (int ks = 0; ks < 2; ks++) {
            uint32_t row = cbase + 16 * mt + arow_off;
            uint32_t kk  = 16 * ks + akk_off;
            LDSM_X4(AH[mt][ks], sb + OFF_AH + row * ROWB + kk * 2);
            LDSM_X4(AL[mt][ks], sb + OFF_AL + row * ROWB + kk * 2);
        }

    // ---- B fragment lane address pieces ----
    // x4 at (j0,k0): mat0 = rows j0..7 k0..7 (nt0 b0), mat1 = j0..7 k0+8 (nt0 b1),
    //                mat2 = j0+8..15 k0..7 (nt1 b0), mat3 = j0+8..15 k0+8 (nt1 b1)
    const int brow_off = ((l >> 4) << 3) + (l & 7);  // 0..15
    const int bkk_off  = (((l >> 3) & 1) << 3);      // 0 or 8

    // bias (folded into acc init)
    float bias0[2], bias1[2];
#pragma unroll
    for (int mt = 0; mt < 2; mt++) {
        bias0[mt] = __ldg(fb + cbase + 16 * mt + gid);
        bias1[mt] = __ldg(fb + cbase + 16 * mt + gid + 8);
    }

    const float* hb = h + (size_t)b * NA * CH;
    float ps[4] = {0.f, 0.f, 0.f, 0.f};   // [mt*2 + rowhi]

#pragma unroll 1
    for (int scnk = 0; scnk < 8; scnk++) {   // 16 j per subchunk
        const int j0 = scnk * 16;
        uint32_t BH0[4], BH1[4], BL0[4], BL1[4];
        {
            uint32_t jrow = (j0 + brow_off) * ROWB;
            LDSM_X4(BH0, sb + OFF_EH + jrow + (0  + bkk_off) * 2);
            LDSM_X4(BH1, sb + OFF_EH + jrow + (16 + bkk_off) * 2);
            LDSM_X4(BL0, sb + OFF_EL + jrow + (0  + bkk_off) * 2);
            LDSM_X4(BL1, sb + OFF_EL + jrow + (16 + bkk_off) * 2);
        }

        float acc[2][2][4];   // [mt][nt][4]
#pragma unroll
        for (int mt = 0; mt < 2; mt++)
#pragma unroll
            for (int nt = 0; nt < 2; nt++) {
                acc[mt][nt][0] = bias0[mt];
                acc[mt][nt][1] = bias0[mt];
                acc[mt][nt][2] = bias1[mt];
                acc[mt][nt][3] = bias1[mt];
            }

#pragma unroll
        for (int mt = 0; mt < 2; mt++)
#pragma unroll
            for (int nt = 0; nt < 2; nt++) {
                float* d = acc[mt][nt];
                // eh*wh
                mma_bf16(d, AH[mt][0], BH0[nt * 2], BH0[nt * 2 + 1]);
                mma_bf16(d, AH[mt][1], BH1[nt * 2], BH1[nt * 2 + 1]);
                // el*wh
                mma_bf16(d, AH[mt][0], BL0[nt * 2], BL0[nt * 2 + 1]);
                mma_bf16(d, AH[mt][1], BL1[nt * 2], BL1[nt * 2 + 1]);
                // eh*wl
                mma_bf16(d, AL[mt][0], BH0[nt * 2], BH0[nt * 2 + 1]);
                mma_bf16(d, AL[mt][1], BH1[nt * 2], BH1[nt * 2 + 1]);
            }

        // epilogue: selu + edge mask + aggregate with h[b,j,c]
#pragma unroll
        for (int nt = 0; nt < 2; nt++) {
            const int jb = j0 + 8 * nt + 2 * tig;
            const float em0 = ems[jb];
            const float em1 = ems[jb + 1];
#pragma unroll
            for (int mt = 0; mt < 2; mt++) {
                const int c0 = cbase + 16 * mt + gid;
                const float h00 = __ldg(hb + (size_t)jb * CH + c0);
                const float h01 = __ldg(hb + (size_t)(jb + 1) * CH + c0);
                const float h10 = __ldg(hb + (size_t)jb * CH + c0 + 8);
                const float h11 = __ldg(hb + (size_t)(jb + 1) * CH + c0 + 8);
                float s0 = selu_f(acc[mt][nt][0]) * em0;
                float s1 = selu_f(acc[mt][nt][1]) * em1;
                float s2 = selu_f(acc[mt][nt][2]) * em0;
                float s3 = selu_f(acc[mt][nt][3]) * em1;
                ps[mt * 2]     = fmaf(s0, h00, fmaf(s1, h01, ps[mt * 2]));
                ps[mt * 2 + 1] = fmaf(s2, h10, fmaf(s3, h11, ps[mt * 2 + 1]));
            }
        }
    }

    // reduce over the quad group (tig): each quad's lanes cover disjoint j
#pragma unroll
    for (int i = 0; i < 4; i++) {
        ps[i] += __shfl_xor_sync(0xffffffffu, ps[i], 1);
        ps[i] += __shfl_xor_sync(0xffffffffu, ps[i], 2);
    }
    if (tig == 0) {
        float* o = g_h1 + (size_t)bi * CH;
#pragma unroll
        for (int mt = 0; mt < 2; mt++) {
            o[cbase + 16 * mt + gid]     = ps[mt * 2];
            o[cbase + 16 * mt + gid + 8] = ps[mt * 2 + 1];
        }
    }
}

// =====================================================================
// Kernel 2: node MLP (unchanged, known-good).
// =====================================================================
#define BM 64
#define BN 64
#define BK 32
#define APAD 68

__global__ void __launch_bounds__(256)
node_mlp_kernel(const float* __restrict__ h,
                const float* __restrict__ nmask,
                const float* __restrict__ wW,
                const float* __restrict__ wb,
                float* __restrict__ out) {
    __shared__ float As[BK][APAD];
    __shared__ float Bs[BK][APAD];

    const int n0  = blockIdx.x * BN;
    const int m0  = blockIdx.y * BM;
    const int tid = threadIdx.x;
    const int tx  = tid & 15;
    const int ty  = tid >> 4;

    unsigned long long acc[4][2];
#pragma unroll
    for (int i = 0; i < 4; i++) { acc[i][0] = 0ULL; acc[i][1] = 0ULL; }

    for (int k0 = 0; k0 < KK; k0 += BK) {
        const float* Asrc = (k0 < CH) ? (h + k0) : (g_h1 + (k0 - CH));
#pragma unroll
        for (int u = 0; u < 8; u++) {
            int idx = tid + u * 256;
            int r = idx >> 5;
            int k = idx & 31;
            As[k][r] = Asrc[(size_t)(m0 + r) * CH + k];
            Bs[k][r] = wW[(size_t)(n0 + r) * KK + k0 + k];
        }
        __syncthreads();

#pragma unroll
        for (int k = 0; k < BK; k++) {
            float4 a = *(const float4*)&As[k][ty * 4];
            ulonglong2 bb = *(const ulonglong2*)&Bs[k][tx * 4];
            unsigned long long a0 = pack2(a.x, a.x);
            unsigned long long a1 = pack2(a.y, a.y);
            unsigned long long a2 = pack2(a.z, a.z);
            unsigned long long a3 = pack2(a.w, a.w);
            fma2(acc[0][0], a0, bb.x); fma2(acc[0][1], a0, bb.y);
            fma2(acc[1][0], a1, bb.x); fma2(acc[1][1], a1, bb.y);
            fma2(acc[2][0], a2, bb.x); fma2(acc[2][1], a2, bb.y);
            fma2(acc[3][0], a3, bb.x); fma2(acc[3][1], a3, bb.y);
        }
        __syncthreads();
    }

    const float4 bv = *(const float4*)(wb + n0 + tx * 4);
#pragma unroll
    for (int i = 0; i < 4; i++) {
        int m = m0 + ty * 4 + i;
        float nmv = nmask[m];
        float v0, v1, v2, v3;
        unpack2(acc[i][0], v0, v1);
        unpack2(acc[i][1], v2, v3);
        const float4 hres = *(const float4*)(h + (size_t)m * CH + n0 + tx * 4);
        float4 o;
        o.x = selu_f(v0 + bv.x) * nmv + hres.x;
        o.y = selu_f(v1 + bv.y) * nmv + hres.y;
        o.z = selu_f(v2 + bv.z) * nmv + hres.z;
        o.w = selu_f(v3 + bv.w) * nmv + hres.w;
        *(float4*)(out + (size_t)m * CH + n0 + tx * 4) = o;
    }
}

// =====================================================================
extern "C" void kernel_launch(void* const* d_in, const int* in_sizes, int n_in,
                              void* d_out, int out_size) {
    (void)in_sizes; (void)n_in; (void)out_size;
    const float* h     = (const float*)d_in[0];
    const float* e     = (const float*)d_in[1];
    const float* nmask = (const float*)d_in[2];
    const float* emask = (const float*)d_in[3];
    const float* fW    = (const float*)d_in[4];
    const float* fb    = (const float*)d_in[5];
    const float* wW    = (const float*)d_in[6];
    const float* wb    = (const float*)d_in[7];
    float* out = (float*)d_out;

    static bool attr_set = false;
    if (!attr_set) {
        cudaFuncSetAttribute(edge_mma_kernel,
                             cudaFuncAttributeMaxDynamicSharedMemorySize, EDGE_SMEM);
        attr_set = true;
    }
    edge_mma_kernel<<<NB * NA, 512, EDGE_SMEM>>>(h, e, emask, fW, fb);
    node_mlp_kernel<<<dim3(CH / BN, (NB * NA) / BM), 256>>>(h, nmask, wW, wb, out);
}

// round 4
// speedup vs baseline: 2.8800x; 2.1216x over previous
#include <cuda_runtime.h>
#include <cuda_fp16.h>
#include <cstdint>

#define NB 16
#define NA 128
#define CH 512
#define EF 30
#define KK 1024   // 2*CH

// h1 scratch as fp16 (2 MB) + precomputed fW A-fragments (32 KB)
__device__ __half  g_h1h[(size_t)NB * NA * CH];
__device__ uint32_t g_afrag[16 * 2 * 2 * 32 * 4];   // [chunk][mt][ks][lane][r]

// selu(x) = scale * (x>0 ? x : alpha*(exp(x)-1))
__device__ __forceinline__ float selu_f(float x) {
    const float sc  = 1.0507009873554805f;
    const float sca = 1.7580993408473766f;  // scale*alpha
    float ex  = __expf(x);
    float neg = fmaf(ex, sca, -sca);
    float pos = sc * x;
    return (x > 0.0f) ? pos : neg;
}

__device__ __forceinline__ uint32_t smem_u32(const void* p) {
    uint32_t a;
    asm("{ .reg .u64 t; cvta.to.shared.u64 t, %1; cvt.u32.u64 %0, t; }" : "=r"(a) : "l"(p));
    return a;
}

#define LDSM_X4(r, addr) \
    asm volatile("ldmatrix.sync.aligned.m8n8.x4.shared.b16 {%0,%1,%2,%3}, [%4];" \
        : "=r"((r)[0]), "=r"((r)[1]), "=r"((r)[2]), "=r"((r)[3]) : "r"(addr))

// mma m16n8k16 fp16 -> f32 (sm_80+)
__device__ __forceinline__ void mma_f16(float* d, uint32_t a0, uint32_t a1,
                                        uint32_t a2, uint32_t a3,
                                        uint32_t b0, uint32_t b1) {
    asm volatile(
        "mma.sync.aligned.m16n8k16.row.col.f32.f16.f16.f32 "
        "{%0,%1,%2,%3}, {%4,%5,%6,%7}, {%8,%9}, {%0,%1,%2,%3};"
        : "+f"(d[0]), "+f"(d[1]), "+f"(d[2]), "+f"(d[3])
        : "r"(a0), "r"(a1), "r"(a2), "r"(a3), "r"(b0), "r"(b1));
}

// =====================================================================
// Setup: precompute fW fp16 A-fragments, fragment-register-ordered.
// Fragment reg r of lane l (for chunk cc, m-tile mt, k-step ks) holds
// fW[cc*32+mt*16+(r&1)*8+(l>>2)][ks*16+(r>>1)*8+(l&3)*2 .. +1], 0-padded.
// =====================================================================
__global__ void __launch_bounds__(256)
prep_afrag_kernel(const float* __restrict__ fW) {
    int idx = blockIdx.x * 256 + threadIdx.x;   // 8192 total
    int r  = idx & 3;
    int l  = (idx >> 2) & 31;
    int ks = (idx >> 7) & 1;
    int mt = (idx >> 8) & 1;
    int cc = idx >> 9;
    int row = cc * 32 + mt * 16 + (r & 1) * 8 + (l >> 2);
    int k   = ks * 16 + (r >> 1) * 8 + (l & 3) * 2;
    float v0 = (k     < EF) ? fW[row * EF + k]     : 0.0f;
    float v1 = (k + 1 < EF) ? fW[row * EF + k + 1] : 0.0f;
    __half2 hv = __floats2half2_rn(v0, v1);
    g_afrag[idx] = *(uint32_t*)&hv;
}

// =====================================================================
// Edge kernel: one CTA per (b, 4 consecutive i). fp16 single-pass MMA.
// D[c,j] = fW[c,:].e[b,i,j,:]; epilogue h1=sum_j selu(D+fb)*em*h.
// smem: e tiles 4 x [128 rows x 80B] (fp16, k padded to 32) + masks.
// =====================================================================
#define EROWB 80

__global__ void __launch_bounds__(512, 2)
edge_mma_kernel(const float* __restrict__ h,
                const float* __restrict__ e,
                const float* __restrict__ emask,
                const float* __restrict__ fb) {
    __shared__ __align__(16) char sE[4 * NA * EROWB];   // 40960 B
    __shared__ float sEms[4 * NA];

    const int tid = threadIdx.x;
    const int bi4 = blockIdx.x;        // b*32 + igrp
    const int b   = bi4 >> 5;
    const int i0  = (bi4 & 31) << 2;

    // zero staging (k=30,31 pad must be 0)
    {
        uint4 z = make_uint4(0, 0, 0, 0);
        uint4* p = (uint4*)sE;
        for (int i = tid; i < (4 * NA * EROWB) / 16; i += 512) p[i] = z;
    }
    __syncthreads();

    // stage e for 4 i's as fp16
    for (int idx = tid; idx < 4 * NA * EF; idx += 512) {
        int ii  = idx / (NA * EF);
        int rem = idx - ii * (NA * EF);
        int r   = rem / EF;
        int c   = rem - r * EF;
        float v = e[((size_t)(b * NA + i0 + ii)) * (NA * EF) + rem];
        *(__half*)(sE + ii * (NA * EROWB) + r * EROWB + c * 2) = __float2half_rn(v);
    }
    {
        int idx = tid;
        if (idx < 4 * NA) {
            int ii = idx >> 7, j = idx & 127;
            sEms[idx] = emask[((size_t)(b * NA + i0 + ii)) * NA + j];
        }
    }
    __syncthreads();

    const int w   = tid >> 5;
    const int l   = tid & 31;
    const int gid = l >> 2;
    const int tig = l & 3;
    const int cbase = w * 32;
    const int brow_off = ((l >> 4) << 3) + (l & 7);
    const int bkk_off  = ((l >> 3) & 1) << 3;

    // A fragments from precomputed global table (uint4 = 4 frag regs)
    uint4 AH[2][2];
#pragma unroll
    for (int mt = 0; mt < 2; mt++)
#pragma unroll
        for (int ks = 0; ks < 2; ks++)
            AH[mt][ks] = *(const uint4*)&g_afrag[(((w * 2 + mt) * 2 + ks) * 32 + l) * 4];

    float bias0[2], bias1[2];
#pragma unroll
    for (int mt = 0; mt < 2; mt++) {
        bias0[mt] = __ldg(fb + cbase + 16 * mt + gid);
        bias1[mt] = __ldg(fb + cbase + 16 * mt + gid + 8);
    }

    const float* hb = h + (size_t)b * NA * CH;
    const uint32_t sbE = smem_u32(sE);

#pragma unroll 1
    for (int ii = 0; ii < 4; ii++) {
        float ps[4] = {0.f, 0.f, 0.f, 0.f};
        const uint32_t ebase = sbE + ii * (NA * EROWB);
        const float* emsp = sEms + ii * NA;

#pragma unroll 1
        for (int sc = 0; sc < 8; sc++) {
            const int j0 = sc * 16;
            uint32_t BH0[4], BH1[4];
            uint32_t jr = ebase + (uint32_t)(j0 + brow_off) * EROWB + bkk_off * 2;
            LDSM_X4(BH0, jr);        // k 0..15
            LDSM_X4(BH1, jr + 32);   // k 16..31

            float acc[2][2][4];
#pragma unroll
            for (int mt = 0; mt < 2; mt++)
#pragma unroll
                for (int nt = 0; nt < 2; nt++) {
                    acc[mt][nt][0] = bias0[mt];
                    acc[mt][nt][1] = bias0[mt];
                    acc[mt][nt][2] = bias1[mt];
                    acc[mt][nt][3] = bias1[mt];
                }

#pragma unroll
            for (int mt = 0; mt < 2; mt++)
#pragma unroll
                for (int nt = 0; nt < 2; nt++) {
                    float* d = acc[mt][nt];
                    mma_f16(d, AH[mt][0].x, AH[mt][0].y, AH[mt][0].z, AH[mt][0].w,
                            BH0[nt * 2], BH0[nt * 2 + 1]);
                    mma_f16(d, AH[mt][1].x, AH[mt][1].y, AH[mt][1].z, AH[mt][1].w,
                            BH1[nt * 2], BH1[nt * 2 + 1]);
                }

            // epilogue: selu + edge mask + aggregate with h[b,j,c]
#pragma unroll
            for (int nt = 0; nt < 2; nt++) {
                const int jb = j0 + 8 * nt + 2 * tig;
                const float em0 = emsp[jb];
                const float em1 = emsp[jb + 1];
#pragma unroll
                for (int mt = 0; mt < 2; mt++) {
                    const int c0 = cbase + 16 * mt + gid;
                    const float h00 = __ldg(hb + (size_t)jb * CH + c0);
                    const float h01 = __ldg(hb + (size_t)(jb + 1) * CH + c0);
                    const float h10 = __ldg(hb + (size_t)jb * CH + c0 + 8);
                    const float h11 = __ldg(hb + (size_t)(jb + 1) * CH + c0 + 8);
                    float s0 = selu_f(acc[mt][nt][0]) * em0;
                    float s1 = selu_f(acc[mt][nt][1]) * em1;
                    float s2 = selu_f(acc[mt][nt][2]) * em0;
                    float s3 = selu_f(acc[mt][nt][3]) * em1;
                    ps[mt * 2]     = fmaf(s0, h00, fmaf(s1, h01, ps[mt * 2]));
                    ps[mt * 2 + 1] = fmaf(s2, h10, fmaf(s3, h11, ps[mt * 2 + 1]));
                }
            }
        }

        // quad-group reduce over j, write h1 as fp16
#pragma unroll
        for (int i = 0; i < 4; i++) {
            ps[i] += __shfl_xor_sync(0xffffffffu, ps[i], 1);
            ps[i] += __shfl_xor_sync(0xffffffffu, ps[i], 2);
        }
        if (tig == 0) {
            __half* o = g_h1h + (size_t)(b * NA + i0 + ii) * CH;
#pragma unroll
            for (int mt = 0; mt < 2; mt++) {
                o[cbase + 16 * mt + gid]     = __float2half_rn(ps[mt * 2]);
                o[cbase + 16 * mt + gid + 8] = __float2half_rn(ps[mt * 2 + 1]);
            }
        }
    }
}

// =====================================================================
// Node MLP: fp16 single-pass mma.sync GEMM, 64x64 tile, K=1024.
// out = selu(z.wW^T + wb)*nmask + h, z = concat(h, h1h).
// =====================================================================
#define NROWH 72   // half elements per smem row (144 B stride)

__global__ void __launch_bounds__(256)
node_mma_kernel(const float* __restrict__ h,
                const float* __restrict__ nmask,
                const float* __restrict__ wW,
                const float* __restrict__ wb,
                float* __restrict__ out) {
    __shared__ __align__(16) __half sA[64][NROWH];
    __shared__ __align__(16) __half sB[64][NROWH];

    const int n0  = blockIdx.x * 64;
    const int m0  = blockIdx.y * 64;
    const int tid = threadIdx.x;
    const int w   = tid >> 5;
    const int l   = tid & 31;
    const int gid = l >> 2;
    const int tig = l & 3;
    const int mtile = w >> 1;   // 0..3
    const int nh    = w & 1;    // 0..1

    float acc[4][4];
#pragma unroll
    for (int nt = 0; nt < 4; nt++) {
        int n = n0 + nh * 32 + nt * 8 + tig * 2;
        float b0 = __ldg(wb + n), b1 = __ldg(wb + n + 1);
        acc[nt][0] = b0; acc[nt][1] = b1;
        acc[nt][2] = b0; acc[nt][3] = b1;
    }

    const int lr  = tid >> 2;   // load row 0..63
    const int seg = tid & 3;    // 16-wide k segment

    const int a_row = mtile * 16 + (l & 15);
    const int a_col_off = (l >> 4) << 3;
    const int b_row_off = nh * 32 + ((l >> 4) << 3) + (l & 7);
    const int b_col_off = ((l >> 3) & 1) << 3;

#pragma unroll 1
    for (int kc = 0; kc < 16; kc++) {
        const int k0 = kc * 64;
        // load A (z) chunk
        if (k0 < CH) {
            const float* src = h + (size_t)(m0 + lr) * CH + k0 + seg * 16;
#pragma unroll
            for (int q = 0; q < 4; q++) {
                float4 f = *(const float4*)(src + q * 4);
                *(__half2*)&sA[lr][seg * 16 + q * 4]     = __floats2half2_rn(f.x, f.y);
                *(__half2*)&sA[lr][seg * 16 + q * 4 + 2] = __floats2half2_rn(f.z, f.w);
            }
        } else {
            const __half* src = g_h1h + (size_t)(m0 + lr) * CH + (k0 - CH) + seg * 16;
            uint4 v0 = *(const uint4*)src;
            uint4 v1 = *(const uint4*)(src + 8);
            *(uint4*)&sA[lr][seg * 16]     = v0;
            *(uint4*)&sA[lr][seg * 16 + 8] = v1;
        }
        // load B (wW) chunk
        {
            const float* src = wW + (size_t)(n0 + lr) * KK + k0 + seg * 16;
#pragma unroll
            for (int q = 0; q < 4; q++) {
                float4 f = *(const float4*)(src + q * 4);
                *(__half2*)&sB[lr][seg * 16 + q * 4]     = __floats2half2_rn(f.x, f.y);
                *(__half2*)&sB[lr][seg * 16 + q * 4 + 2] = __floats2half2_rn(f.z, f.w);
            }
        }
        __syncthreads();

#pragma unroll
        for (int ks = 0; ks < 4; ks++) {
            uint32_t Af[4];
            LDSM_X4(Af, smem_u32(&sA[a_row][ks * 16 + a_col_off]));
            uint32_t Bf0[4], Bf1[4];
            LDSM_X4(Bf0, smem_u32(&sB[b_row_off][ks * 16 + b_col_off]));
            LDSM_X4(Bf1, smem_u32(&sB[b_row_off + 16][ks * 16 + b_col_off]));
            mma_f16(acc[0], Af[0], Af[1], Af[2], Af[3], Bf0[0], Bf0[1]);
            mma_f16(acc[1], Af[0], Af[1], Af[2], Af[3], Bf0[2], Bf0[3]);
            mma_f16(acc[2], Af[0], Af[1], Af[2], Af[3], Bf1[0], Bf1[1]);
            mma_f16(acc[3], Af[0], Af[1], Af[2], Af[3], Bf1[2], Bf1[3]);
        }
        __syncthreads();
    }

    // epilogue: selu + node mask + residual
    const int m = m0 + mtile * 16 + gid;
    const float nm0 = __ldg(nmask + m);
    const float nm1 = __ldg(nmask + m + 8);
#pragma unroll
    for (int nt = 0; nt < 4; nt++) {
        int n = n0 + nh * 32 + nt * 8 + tig * 2;
        float2 hr0 = *(const float2*)(h + (size_t)m * CH + n);
        float2 hr1 = *(const float2*)(h + (size_t)(m + 8) * CH + n);
        float2 o0, o1;
        o0.x = selu_f(acc[nt][0]) * nm0 + hr0.x;
        o0.y = selu_f(acc[nt][1]) * nm0 + hr0.y;
        o1.x = selu_f(acc[nt][2]) * nm1 + hr1.x;
        o1.y = selu_f(acc[nt][3]) * nm1 + hr1.y;
        *(float2*)(out + (size_t)m * CH + n)       = o0;
        *(float2*)(out + (size_t)(m + 8) * CH + n) = o1;
    }
}

// =====================================================================
extern "C" void kernel_launch(void* const* d_in, const int* in_sizes, int n_in,
                              void* d_out, int out_size) {
    (void)in_sizes; (void)n_in; (void)out_size;
    const float* h     = (const float*)d_in[0];
    const float* e     = (const float*)d_in[1];
    const float* nmask = (const float*)d_in[2];
    const float* emask = (const float*)d_in[3];
    const float* fW    = (const float*)d_in[4];
    const float* fb    = (const float*)d_in[5];
    const float* wW    = (const float*)d_in[6];
    const float* wb    = (const float*)d_in[7];
    float* out = (float*)d_out;

    prep_afrag_kernel<<<32, 256>>>(fW);
    edge_mma_kernel<<<NB * 32, 512>>>(h, e, emask, fb);
    node_mma_kernel<<<dim3(CH / 64, (NB * NA) / 64), 256>>>(h, nmask, wW, wb, out);
}

// round 5
// speedup vs baseline: 3.0742x; 1.0674x over previous
#include <cuda_runtime.h>
#include <cuda_fp16.h>
#include <cstdint>

#define NB 16
#define NA 128
#define CH 512
#define EF 30
#define KK 1024   // 2*CH

// device scratch (allocation-free)
__device__ __half   g_h1h[(size_t)NB * NA * CH];    // h1 result, fp16
__device__ __half   g_hh [(size_t)NB * NA * CH];    // h as fp16 (MMA operand)
__device__ __half   g_wWh[(size_t)CH * KK];         // w_W as fp16
__device__ uint32_t g_afrag[16 * 2 * 2 * 32 * 4];   // fW A-fragments

// selu(x) = scale * (x>0 ? x : alpha*(exp(x)-1))
__device__ __forceinline__ float selu_f(float x) {
    const float sc  = 1.0507009873554805f;
    const float sca = 1.7580993408473766f;  // scale*alpha
    float ex  = __expf(x);
    float neg = fmaf(ex, sca, -sca);
    float pos = sc * x;
    return (x > 0.0f) ? pos : neg;
}

__device__ __forceinline__ uint32_t smem_u32(const void* p) {
    uint32_t a;
    asm("{ .reg .u64 t; cvta.to.shared.u64 t, %1; cvt.u32.u64 %0, t; }" : "=r"(a) : "l"(p));
    return a;
}

#define LDSM_X4(r, addr) \
    asm volatile("ldmatrix.sync.aligned.m8n8.x4.shared.b16 {%0,%1,%2,%3}, [%4];" \
        : "=r"((r)[0]), "=r"((r)[1]), "=r"((r)[2]), "=r"((r)[3]) : "r"(addr))

__device__ __forceinline__ void mma_f16(float* d, uint32_t a0, uint32_t a1,
                                        uint32_t a2, uint32_t a3,
                                        uint32_t b0, uint32_t b1) {
    asm volatile(
        "mma.sync.aligned.m16n8k16.row.col.f32.f16.f16.f32 "
        "{%0,%1,%2,%3}, {%4,%5,%6,%7}, {%8,%9}, {%0,%1,%2,%3};"
        : "+f"(d[0]), "+f"(d[1]), "+f"(d[2]), "+f"(d[3])
        : "r"(a0), "r"(a1), "r"(a2), "r"(a3), "r"(b0), "r"(b1));
}

// =====================================================================
// Prep: fW A-fragments + fp16 conversions of h and wW (one launch).
// =====================================================================
__global__ void __launch_bounds__(256)
prep_kernel(const float* __restrict__ fW, const float* __restrict__ wW,
            const float* __restrict__ h) {
    const int t = blockIdx.x * 256 + threadIdx.x;
    const int stride = gridDim.x * 256;

    // h -> fp16 (262144 float4)
    for (int i = t; i < (NB * NA * CH) / 4; i += stride) {
        float4 f = ((const float4*)h)[i];
        ((__half2*)g_hh)[i * 2]     = __floats2half2_rn(f.x, f.y);
        ((__half2*)g_hh)[i * 2 + 1] = __floats2half2_rn(f.z, f.w);
    }
    // wW -> fp16 (131072 float4)
    for (int i = t; i < (CH * KK) / 4; i += stride) {
        float4 f = ((const float4*)wW)[i];
        ((__half2*)g_wWh)[i * 2]     = __floats2half2_rn(f.x, f.y);
        ((__half2*)g_wWh)[i * 2 + 1] = __floats2half2_rn(f.z, f.w);
    }
    // fW fragments, fragment-register-ordered (verified layout)
    for (int idx = t; idx < 8192; idx += stride) {
        int r  = idx & 3;
        int l  = (idx >> 2) & 31;
        int ks = (idx >> 7) & 1;
        int mt = (idx >> 8) & 1;
        int cc = idx >> 9;
        int row = cc * 32 + mt * 16 + (r & 1) * 8 + (l >> 2);
        int k   = ks * 16 + (r >> 1) * 8 + (l & 3) * 2;
        float v0 = (k     < EF) ? fW[row * EF + k]     : 0.0f;
        float v1 = (k + 1 < EF) ? fW[row * EF + k + 1] : 0.0f;
        __half2 hv = __floats2half2_rn(v0, v1);
        g_afrag[idx] = *(uint32_t*)&hv;
    }
}

// =====================================================================
// Edge kernel: one CTA per (b, 4 consecutive i). fp16 single-pass MMA.
// =====================================================================
#define EROWB 80

__global__ void __launch_bounds__(512, 2)
edge_mma_kernel(const float* __restrict__ e,
                const float* __restrict__ emask,
                const float* __restrict__ fb) {
    __shared__ __align__(16) char sE[4 * NA * EROWB];   // 40960 B
    __shared__ float sEms[4 * NA];

    const int tid = threadIdx.x;
    const int bi4 = blockIdx.x;        // b*32 + igrp
    const int b   = bi4 >> 5;
    const int i0  = (bi4 & 31) << 2;

    // zero staging (k pad must be 0)
    {
        uint4 z = make_uint4(0, 0, 0, 0);
        uint4* p = (uint4*)sE;
        for (int i = tid; i < (4 * NA * EROWB) / 16; i += 512) p[i] = z;
    }
    __syncthreads();

    for (int idx = tid; idx < 4 * NA * EF; idx += 512) {
        int ii  = idx / (NA * EF);
        int rem = idx - ii * (NA * EF);
        int r   = rem / EF;
        int c   = rem - r * EF;
        float v = e[((size_t)(b * NA + i0 + ii)) * (NA * EF) + rem];
        *(__half*)(sE + ii * (NA * EROWB) + r * EROWB + c * 2) = __float2half_rn(v);
    }
    if (tid < 4 * NA) {
        int ii = tid >> 7, j = tid & 127;
        sEms[tid] = emask[((size_t)(b * NA + i0 + ii)) * NA + j];
    }
    __syncthreads();

    const int w   = tid >> 5;
    const int l   = tid & 31;
    const int gid = l >> 2;
    const int tig = l & 3;
    const int cbase = w * 32;
    const int brow_off = ((l >> 4) << 3) + (l & 7);
    const int bkk_off  = ((l >> 3) & 1) << 3;

    uint4 AH[2][2];
#pragma unroll
    for (int mt = 0; mt < 2; mt++)
#pragma unroll
        for (int ks = 0; ks < 2; ks++)
            AH[mt][ks] = *(const uint4*)&g_afrag[(((w * 2 + mt) * 2 + ks) * 32 + l) * 4];

    float bias0[2], bias1[2];
#pragma unroll
    for (int mt = 0; mt < 2; mt++) {
        bias0[mt] = __ldg(fb + cbase + 16 * mt + gid);
        bias1[mt] = __ldg(fb + cbase + 16 * mt + gid + 8);
    }

    const __half* hb = g_hh + (size_t)b * NA * CH;
    const uint32_t sbE = smem_u32(sE);

#pragma unroll 1
    for (int ii = 0; ii < 4; ii++) {
        float ps[4] = {0.f, 0.f, 0.f, 0.f};
        const uint32_t ebase = sbE + ii * (NA * EROWB);
        const float* emsp = sEms + ii * NA;

#pragma unroll 1
        for (int sc = 0; sc < 8; sc++) {
            const int j0 = sc * 16;
            uint32_t BH0[4], BH1[4];
            uint32_t jr = ebase + (uint32_t)(j0 + brow_off) * EROWB + bkk_off * 2;
            LDSM_X4(BH0, jr);        // k 0..15
            LDSM_X4(BH1, jr + 32);   // k 16..31

            // prefetch h values for this subchunk (fp16, L1-resident)
            float hv[2][2][4];   // [nt][mt][{00,01,10,11}]
#pragma unroll
            for (int nt = 0; nt < 2; nt++) {
                const int jb = j0 + 8 * nt + 2 * tig;
#pragma unroll
                for (int mt = 0; mt < 2; mt++) {
                    const int c0 = cbase + 16 * mt + gid;
                    hv[nt][mt][0] = __half2float(__ldg(hb + (size_t)jb * CH + c0));
                    hv[nt][mt][1] = __half2float(__ldg(hb + (size_t)(jb + 1) * CH + c0));
                    hv[nt][mt][2] = __half2float(__ldg(hb + (size_t)jb * CH + c0 + 8));
                    hv[nt][mt][3] = __half2float(__ldg(hb + (size_t)(jb + 1) * CH + c0 + 8));
                }
            }

            float acc[2][2][4];
#pragma unroll
            for (int mt = 0; mt < 2; mt++)
#pragma unroll
                for (int nt = 0; nt < 2; nt++) {
                    acc[mt][nt][0] = bias0[mt];
                    acc[mt][nt][1] = bias0[mt];
                    acc[mt][nt][2] = bias1[mt];
                    acc[mt][nt][3] = bias1[mt];
                }

#pragma unroll
            for (int mt = 0; mt < 2; mt++)
#pragma unroll
                for (int nt = 0; nt < 2; nt++) {
                    float* d = acc[mt][nt];
                    mma_f16(d, AH[mt][0].x, AH[mt][0].y, AH[mt][0].z, AH[mt][0].w,
                            BH0[nt * 2], BH0[nt * 2 + 1]);
                    mma_f16(d, AH[mt][1].x, AH[mt][1].y, AH[mt][1].z, AH[mt][1].w,
                            BH1[nt * 2], BH1[nt * 2 + 1]);
                }

#pragma unroll
            for (int nt = 0; nt < 2; nt++) {
                const int jb = j0 + 8 * nt + 2 * tig;
                const float em0 = emsp[jb];
                const float em1 = emsp[jb + 1];
#pragma unroll
                for (int mt = 0; mt < 2; mt++) {
                    float s0 = selu_f(acc[mt][nt][0]) * em0;
                    float s1 = selu_f(acc[mt][nt][1]) * em1;
                    float s2 = selu_f(acc[mt][nt][2]) * em0;
                    float s3 = selu_f(acc[mt][nt][3]) * em1;
                    ps[mt * 2]     = fmaf(s0, hv[nt][mt][0], fmaf(s1, hv[nt][mt][1], ps[mt * 2]));
                    ps[mt * 2 + 1] = fmaf(s2, hv[nt][mt][2], fmaf(s3, hv[nt][mt][3], ps[mt * 2 + 1]));
                }
            }
        }

#pragma unroll
        for (int i = 0; i < 4; i++) {
            ps[i] += __shfl_xor_sync(0xffffffffu, ps[i], 1);
            ps[i] += __shfl_xor_sync(0xffffffffu, ps[i], 2);
        }
        if (tig == 0) {
            __half* o = g_h1h + (size_t)(b * NA + i0 + ii) * CH;
#pragma unroll
            for (int mt = 0; mt < 2; mt++) {
                o[cbase + 16 * mt + gid]     = __float2half_rn(ps[mt * 2]);
                o[cbase + 16 * mt + gid + 8] = __float2half_rn(ps[mt * 2 + 1]);
            }
        }
    }
}

// =====================================================================
// Node MLP: 128x64 tile, 256 threads, register double-buffered loads,
// all-fp16 operands (pre-converted). K=1024 in 16 chunks of 64.
// =====================================================================
#define NROWH 72

__global__ void __launch_bounds__(256)
node_mma_kernel(const float* __restrict__ h,
                const float* __restrict__ nmask,
                const float* __restrict__ wb,
                float* __restrict__ out) {
    __shared__ __align__(16) __half sA[128][NROWH];
    __shared__ __align__(16) __half sB[64][NROWH];

    const int n0  = blockIdx.x * 64;
    const int m0  = blockIdx.y * 128;
    const int tid = threadIdx.x;
    const int w   = tid >> 5;
    const int l   = tid & 31;
    const int gid = l >> 2;
    const int tig = l & 3;
    const int mw  = w >> 1;   // 0..3 (32 m-rows per warp)
    const int nh  = w & 1;    // 0..1 (32 n-cols per warp)

    float acc[2][4][4];
#pragma unroll
    for (int nt = 0; nt < 4; nt++) {
        int n = n0 + nh * 32 + nt * 8 + tig * 2;
        float b0 = __ldg(wb + n), b1 = __ldg(wb + n + 1);
#pragma unroll
        for (int mt = 0; mt < 2; mt++) {
            acc[mt][nt][0] = b0; acc[mt][nt][1] = b1;
            acc[mt][nt][2] = b0; acc[mt][nt][3] = b1;
        }
    }

    const int arow = mw * 32 + (l & 15);
    const int acol = (l >> 4) << 3;
    const int brow = nh * 32 + ((l >> 4) << 3) + (l & 7);
    const int bcol = ((l >> 3) & 1) << 3;

    uint4 ld[6];
    // per-thread load coords (fixed)
    int lrow[6], lseg[6], lisA[6];
#pragma unroll
    for (int q = 0; q < 6; q++) {
        int cid = q * 256 + tid;          // 0..1535
        lisA[q] = (cid < 1024);
        int c2 = lisA[q] ? cid : cid - 1024;
        lrow[q] = c2 >> 3;
        lseg[q] = c2 & 7;
    }

#define LOAD_TILE(kc) do { \
    _Pragma("unroll") \
    for (int q = 0; q < 6; q++) { \
        if (lisA[q]) { \
            const __half* src = ((kc) < 8) \
                ? (g_hh  + (size_t)(m0 + lrow[q]) * CH + (kc) * 64 + lseg[q] * 8) \
                : (g_h1h + (size_t)(m0 + lrow[q]) * CH + ((kc) - 8) * 64 + lseg[q] * 8); \
            ld[q] = *(const uint4*)src; \
        } else { \
            ld[q] = *(const uint4*)(g_wWh + (size_t)(n0 + lrow[q]) * KK + (kc) * 64 + lseg[q] * 8); \
        } \
    } \
} while (0)

    LOAD_TILE(0);

#pragma unroll 1
    for (int kc = 0; kc < 16; kc++) {
        __syncthreads();   // prior MMA reads done before overwrite
#pragma unroll
        for (int q = 0; q < 6; q++) {
            if (lisA[q]) *(uint4*)&sA[lrow[q]][lseg[q] * 8] = ld[q];
            else         *(uint4*)&sB[lrow[q]][lseg[q] * 8] = ld[q];
        }
        __syncthreads();
        if (kc < 15) LOAD_TILE(kc + 1);   // overlap next loads with MMA

#pragma unroll
        for (int ks = 0; ks < 4; ks++) {
            uint32_t Af[2][4];
            LDSM_X4(Af[0], smem_u32(&sA[arow][ks * 16 + acol]));
            LDSM_X4(Af[1], smem_u32(&sA[arow + 16][ks * 16 + acol]));
            uint32_t Bf0[4], Bf1[4];
            LDSM_X4(Bf0, smem_u32(&sB[brow][ks * 16 + bcol]));
            LDSM_X4(Bf1, smem_u32(&sB[brow + 16][ks * 16 + bcol]));
#pragma unroll
            for (int mt = 0; mt < 2; mt++) {
                mma_f16(acc[mt][0], Af[mt][0], Af[mt][1], Af[mt][2], Af[mt][3], Bf0[0], Bf0[1]);
                mma_f16(acc[mt][1], Af[mt][0], Af[mt][1], Af[mt][2], Af[mt][3], Bf0[2], Bf0[3]);
                mma_f16(acc[mt][2], Af[mt][0], Af[mt][1], Af[mt][2], Af[mt][3], Bf1[0], Bf1[1]);
                mma_f16(acc[mt][3], Af[mt][0], Af[mt][1], Af[mt][2], Af[mt][3], Bf1[2], Bf1[3]);
            }
        }
    }

    // epilogue: selu + node mask + residual (fp32 h for residual)
#pragma unroll
    for (int mt = 0; mt < 2; mt++) {
        const int m = m0 + mw * 32 + mt * 16 + gid;
        const float nm0 = __ldg(nmask + m);
        const float nm1 = __ldg(nmask + m + 8);
#pragma unroll
        for (int nt = 0; nt < 4; nt++) {
            int n = n0 + nh * 32 + nt * 8 + tig * 2;
            float2 hr0 = *(const float2*)(h + (size_t)m * CH + n);
            float2 hr1 = *(const float2*)(h + (size_t)(m + 8) * CH + n);
            float2 o0, o1;
            o0.x = selu_f(acc[mt][nt][0]) * nm0 + hr0.x;
            o0.y = selu_f(acc[mt][nt][1]) * nm0 + hr0.y;
            o1.x = selu_f(acc[mt][nt][2]) * nm1 + hr1.x;
            o1.y = selu_f(acc[mt][nt][3]) * nm1 + hr1.y;
            *(float2*)(out + (size_t)m * CH + n)       = o0;
            *(float2*)(out + (size_t)(m + 8) * CH + n) = o1;
        }
    }
}

// =====================================================================
extern "C" void kernel_launch(void* const* d_in, const int* in_sizes, int n_in,
                              void* d_out, int out_size) {
    (void)in_sizes; (void)n_in; (void)out_size;
    const float* h     = (const float*)d_in[0];
    const float* e     = (const float*)d_in[1];
    const float* nmask = (const float*)d_in[2];
    const float* emask = (const float*)d_in[3];
    const float* fW    = (const float*)d_in[4];
    const float* fb    = (const float*)d_in[5];
    const float* wW    = (const float*)d_in[6];
    const float* wb    = (const float*)d_in[7];
    float* out = (float*)d_out;

    prep_kernel<<<512, 256>>>(fW, wW, h);
    edge_mma_kernel<<<NB * 32, 512>>>(e, emask, fb);
    node_mma_kernel<<<dim3(CH / 64, (NB * NA) / 128), 256>>>(h, nmask, wb, out);
}

// round 6
// speedup vs baseline: 4.9142x; 1.5985x over previous
#include <cuda_runtime.h>
#include <cuda_fp16.h>
#include <cstdint>

#define NB 16
#define NA 128
#define CH 512
#define EF 30
#define KK 1024   // 2*CH

// device scratch (allocation-free, zero-initialized at load)
__device__ __half   g_h1h[(size_t)NB * NA * CH];    // h1 result, fp16 (masked rows stay 0)
__device__ __half   g_hh [(size_t)NB * NA * CH];    // h as fp16 (MMA operand)
__device__ __half   g_wWh[(size_t)CH * KK];         // w_W as fp16
__device__ uint32_t g_afrag[16 * 2 * 2 * 32 * 4];   // fW A-fragments
__device__ int      g_Mact;                         // # active node rows
__device__ int      g_rowidx[NB * NA];              // active rows first, then masked

// selu(x) = scale * (x>0 ? x : alpha*(exp(x)-1))
__device__ __forceinline__ float selu_f(float x) {
    const float sc  = 1.0507009873554805f;
    const float sca = 1.7580993408473766f;  // scale*alpha
    float ex  = __expf(x);
    float neg = fmaf(ex, sca, -sca);
    float pos = sc * x;
    return (x > 0.0f) ? pos : neg;
}

__device__ __forceinline__ uint32_t smem_u32(const void* p) {
    uint32_t a;
    asm("{ .reg .u64 t; cvta.to.shared.u64 t, %1; cvt.u32.u64 %0, t; }" : "=r"(a) : "l"(p));
    return a;
}

#define LDSM_X4(r, addr) \
    asm volatile("ldmatrix.sync.aligned.m8n8.x4.shared.b16 {%0,%1,%2,%3}, [%4];" \
        : "=r"((r)[0]), "=r"((r)[1]), "=r"((r)[2]), "=r"((r)[3]) : "r"(addr))

__device__ __forceinline__ void mma_f16(float* d, uint32_t a0, uint32_t a1,
                                        uint32_t a2, uint32_t a3,
                                        uint32_t b0, uint32_t b1) {
    asm volatile(
        "mma.sync.aligned.m16n8k16.row.col.f32.f16.f16.f32 "
        "{%0,%1,%2,%3}, {%4,%5,%6,%7}, {%8,%9}, {%0,%1,%2,%3};"
        : "+f"(d[0]), "+f"(d[1]), "+f"(d[2]), "+f"(d[3])
        : "r"(a0), "r"(a1), "r"(a2), "r"(a3), "r"(b0), "r"(b1));
}

// =====================================================================
// Prep: fp16 conversions + fW fragments + node-row compaction scan.
// =====================================================================
__global__ void __launch_bounds__(256)
prep_kernel(const float* __restrict__ fW, const float* __restrict__ wW,
            const float* __restrict__ h, const float* __restrict__ nmask) {
    const int t = blockIdx.x * 256 + threadIdx.x;
    const int stride = gridDim.x * 256;

    for (int i = t; i < (NB * NA * CH) / 4; i += stride) {
        float4 f = ((const float4*)h)[i];
        ((__half2*)g_hh)[i * 2]     = __floats2half2_rn(f.x, f.y);
        ((__half2*)g_hh)[i * 2 + 1] = __floats2half2_rn(f.z, f.w);
    }
    for (int i = t; i < (CH * KK) / 4; i += stride) {
        float4 f = ((const float4*)wW)[i];
        ((__half2*)g_wWh)[i * 2]     = __floats2half2_rn(f.x, f.y);
        ((__half2*)g_wWh)[i * 2 + 1] = __floats2half2_rn(f.z, f.w);
    }
    for (int idx = t; idx < 8192; idx += stride) {
        int r  = idx & 3;
        int l  = (idx >> 2) & 31;
        int ks = (idx >> 7) & 1;
        int mt = (idx >> 8) & 1;
        int cc = idx >> 9;
        int row = cc * 32 + mt * 16 + (r & 1) * 8 + (l >> 2);
        int k   = ks * 16 + (r >> 1) * 8 + (l & 3) * 2;
        float v0 = (k     < EF) ? fW[row * EF + k]     : 0.0f;
        float v1 = (k + 1 < EF) ? fW[row * EF + k + 1] : 0.0f;
        __half2 hv = __floats2half2_rn(v0, v1);
        g_afrag[idx] = *(uint32_t*)&hv;
    }

    // block 0: stable partition of 2048 node rows (active first)
    if (blockIdx.x == 0) {
        __shared__ int cnt[256];
        __shared__ int totalS;
        const int tt = threadIdx.x;
        bool p[8];
        int local = 0;
#pragma unroll
        for (int q = 0; q < 8; q++) {
            int r = tt * 8 + q;
            p[q] = nmask[r] > 0.5f;
            local += p[q];
        }
        cnt[tt] = local;
        __syncthreads();
        if (tt == 0) {
            int s = 0;
            for (int i = 0; i < 256; i++) { int c = cnt[i]; cnt[i] = s; s += c; }
            totalS = s;
            g_Mact = s;
        }
        __syncthreads();
        int aoff = cnt[tt];
        int moff = tt * 8 - aoff;
        const int M = totalS;
#pragma unroll
        for (int q = 0; q < 8; q++) {
            int r = tt * 8 + q;
            if (p[q]) g_rowidx[aoff++] = r;
            else      g_rowidx[M + moff++] = r;
        }
    }
}

// =====================================================================
// Edge kernel: one CTA per (b, 4 consecutive i).
// Skips i with node_mask=0; compacts j by edge_mask (warp ballot).
// =====================================================================
#define EROWB 80

__global__ void __launch_bounds__(512, 2)
edge_mma_kernel(const float* __restrict__ e,
                const float* __restrict__ emask,
                const float* __restrict__ nmask,
                const float* __restrict__ fb) {
    __shared__ __align__(16) char sE[4 * NA * EROWB];   // 40960 B
    __shared__ int   sJ[4][NA];
    __shared__ float sEm[4][NA];
    __shared__ int   sNj[4];
    __shared__ int   sAct[4];
    __shared__ int   sWc[4][4];

    const int tid = threadIdx.x;
    const int bi4 = blockIdx.x;        // b*32 + igrp
    const int b   = bi4 >> 5;
    const int i0  = (bi4 & 31) << 2;

    // zero staging (pad rows/slots must be 0)
    {
        uint4 z = make_uint4(0, 0, 0, 0);
        uint4* p = (uint4*)sE;
        for (int i = tid; i < (4 * NA * EROWB) / 16; i += 512) p[i] = z;
        sJ[tid >> 7][tid & 127]  = 0;     // 512 threads == 4*128 entries
        sEm[tid >> 7][tid & 127] = 0.0f;
    }
    __syncthreads();

    // ---- j compaction per i (group g = tid>>7 handles ii=g) ----
    const int g  = tid >> 7;
    const int t  = tid & 127;
    const int wg = (tid >> 5) & 3;
    const int l  = tid & 31;
    {
        float mv = emask[(size_t)(b * NA + i0 + g) * NA + t];
        bool pred = mv > 0.5f;
        unsigned bal = __ballot_sync(0xffffffffu, pred);
        int pos = __popc(bal & ((1u << l) - 1u));
        if (l == 0) sWc[g][wg] = __popc(bal);
        __syncthreads();
        int off = 0;
#pragma unroll
        for (int k = 0; k < 3; k++) if (k < wg) off += sWc[g][k];
        if (pred) {
            int s = off + pos;
            sJ[g][s]  = t;
            sEm[g][s] = 1.0f;
        }
        if (t == 0) sNj[g] = sWc[g][0] + sWc[g][1] + sWc[g][2] + sWc[g][3];
        if (tid < 4) sAct[tid] = (nmask[(size_t)(b * NA + i0 + tid)] > 0.5f) ? 1 : 0;
    }
    __syncthreads();

    // ---- stage e rows for active i / compacted j ----
    for (int idx = tid; idx < 4 * NA * EF; idx += 512) {
        int gg  = idx / (NA * EF);
        int rem = idx - gg * (NA * EF);
        int s   = rem / EF;
        int c   = rem - s * EF;
        if (!sAct[gg] || s >= sNj[gg]) continue;
        int j = sJ[gg][s];
        float v = e[(size_t)(b * NA + i0 + gg) * (NA * EF) + j * EF + c];
        *(__half*)(sE + gg * (NA * EROWB) + s * EROWB + c * 2) = __float2half_rn(v);
    }
    __syncthreads();

    const int w     = tid >> 5;
    const int gid   = l >> 2;
    const int tig   = l & 3;
    const int cbase = w * 32;
    const int brow_off = ((l >> 4) << 3) + (l & 7);
    const int bkk_off  = ((l >> 3) & 1) << 3;

    uint4 AH[2][2];
#pragma unroll
    for (int mt = 0; mt < 2; mt++)
#pragma unroll
        for (int ks = 0; ks < 2; ks++)
            AH[mt][ks] = *(const uint4*)&g_afrag[(((w * 2 + mt) * 2 + ks) * 32 + l) * 4];

    float bias0[2], bias1[2];
#pragma unroll
    for (int mt = 0; mt < 2; mt++) {
        bias0[mt] = __ldg(fb + cbase + 16 * mt + gid);
        bias1[mt] = __ldg(fb + cbase + 16 * mt + gid + 8);
    }

    const __half* hb = g_hh + (size_t)b * NA * CH;
    const uint32_t sbE = smem_u32(sE);

#pragma unroll 1
    for (int ii = 0; ii < 4; ii++) {
        if (!sAct[ii]) continue;
        const int nsc = (sNj[ii] + 15) >> 4;
        float ps[4] = {0.f, 0.f, 0.f, 0.f};
        const uint32_t ebase = sbE + ii * (NA * EROWB);

#pragma unroll 1
        for (int sc = 0; sc < nsc; sc++) {
            const int j0 = sc * 16;
            uint32_t BH0[4], BH1[4];
            uint32_t jr = ebase + (uint32_t)(j0 + brow_off) * EROWB + bkk_off * 2;
            LDSM_X4(BH0, jr);        // k 0..15
            LDSM_X4(BH1, jr + 32);   // k 16..31

            // gather h values via compacted j indices (fp16, L1-resident)
            int jsA[2], jsB[2];
            float em0[2], em1[2];
#pragma unroll
            for (int nt = 0; nt < 2; nt++) {
                const int slot = j0 + 8 * nt + 2 * tig;
                jsA[nt] = sJ[ii][slot];
                jsB[nt] = sJ[ii][slot + 1];
                em0[nt] = sEm[ii][slot];
                em1[nt] = sEm[ii][slot + 1];
            }
            float hv[2][2][4];
#pragma unroll
            for (int nt = 0; nt < 2; nt++)
#pragma unroll
                for (int mt = 0; mt < 2; mt++) {
                    const int c0 = cbase + 16 * mt + gid;
                    hv[nt][mt][0] = __half2float(__ldg(hb + (size_t)jsA[nt] * CH + c0));
                    hv[nt][mt][1] = __half2float(__ldg(hb + (size_t)jsB[nt] * CH + c0));
                    hv[nt][mt][2] = __half2float(__ldg(hb + (size_t)jsA[nt] * CH + c0 + 8));
                    hv[nt][mt][3] = __half2float(__ldg(hb + (size_t)jsB[nt] * CH + c0 + 8));
                }

            float acc[2][2][4];
#pragma unroll
            for (int mt = 0; mt < 2; mt++)
#pragma unroll
                for (int nt = 0; nt < 2; nt++) {
                    acc[mt][nt][0] = bias0[mt];
                    acc[mt][nt][1] = bias0[mt];
                    acc[mt][nt][2] = bias1[mt];
                    acc[mt][nt][3] = bias1[mt];
                }

#pragma unroll
            for (int mt = 0; mt < 2; mt++)
#pragma unroll
                for (int nt = 0; nt < 2; nt++) {
                    float* d = acc[mt][nt];
                    mma_f16(d, AH[mt][0].x, AH[mt][0].y, AH[mt][0].z, AH[mt][0].w,
                            BH0[nt * 2], BH0[nt * 2 + 1]);
                    mma_f16(d, AH[mt][1].x, AH[mt][1].y, AH[mt][1].z, AH[mt][1].w,
                            BH1[nt * 2], BH1[nt * 2 + 1]);
                }

#pragma unroll
            for (int nt = 0; nt < 2; nt++)
#pragma unroll
                for (int mt = 0; mt < 2; mt++) {
                    float s0 = selu_f(acc[mt][nt][0]) * em0[nt];
                    float s1 = selu_f(acc[mt][nt][1]) * em1[nt];
                    float s2 = selu_f(acc[mt][nt][2]) * em0[nt];
                    float s3 = selu_f(acc[mt][nt][3]) * em1[nt];
                    ps[mt * 2]     = fmaf(s0, hv[nt][mt][0], fmaf(s1, hv[nt][mt][1], ps[mt * 2]));
                    ps[mt * 2 + 1] = fmaf(s2, hv[nt][mt][2], fmaf(s3, hv[nt][mt][3], ps[mt * 2 + 1]));
                }
        }

#pragma unroll
        for (int i = 0; i < 4; i++) {
            ps[i] += __shfl_xor_sync(0xffffffffu, ps[i], 1);
            ps[i] += __shfl_xor_sync(0xffffffffu, ps[i], 2);
        }
        if (tig == 0) {
            __half* o = g_h1h + (size_t)(b * NA + i0 + ii) * CH;
#pragma unroll
            for (int mt = 0; mt < 2; mt++) {
                o[cbase + 16 * mt + gid]     = __float2half_rn(ps[mt * 2]);
                o[cbase + 16 * mt + gid + 8] = __float2half_rn(ps[mt * 2 + 1]);
            }
        }
    }
}

// =====================================================================
// Node MLP: 128x64 tile over COMPACTED rows (active first). Fully-masked
// CTAs degrade to out=h copy. All-fp16 operands, double-buffered loads.
// =====================================================================
#define NROWH 72

__global__ void __launch_bounds__(256)
node_mma_kernel(const float* __restrict__ h,
                const float* __restrict__ nmask,
                const float* __restrict__ wb,
                float* __restrict__ out) {
    __shared__ __align__(16) __half sA[128][NROWH];
    __shared__ __align__(16) __half sB[64][NROWH];
    __shared__ int sRow[128];

    const int n0  = blockIdx.x * 64;
    const int m0  = blockIdx.y * 128;
    const int tid = threadIdx.x;

    if (tid < 128) sRow[tid] = g_rowidx[m0 + tid];
    __syncthreads();

    const int Mact = g_Mact;
    if (m0 >= Mact) {
        // all rows masked: out = h (only n-block 0 CTAs do the copy)
        if (n0 == 0) {
            for (int idx = tid; idx < 128 * 128; idx += 256) {
                int r = idx >> 7, c4 = idx & 127;
                int orig = sRow[r];
                ((float4*)(out + (size_t)orig * CH))[c4] =
                    ((const float4*)(h + (size_t)orig * CH))[c4];
            }
        }
        return;
    }

    const int w   = tid >> 5;
    const int l   = tid & 31;
    const int gid = l >> 2;
    const int tig = l & 3;
    const int mw  = w >> 1;
    const int nh  = w & 1;

    float acc[2][4][4];
#pragma unroll
    for (int nt = 0; nt < 4; nt++) {
        int n = n0 + nh * 32 + nt * 8 + tig * 2;
        float b0 = __ldg(wb + n), b1 = __ldg(wb + n + 1);
#pragma unroll
        for (int mt = 0; mt < 2; mt++) {
            acc[mt][nt][0] = b0; acc[mt][nt][1] = b1;
            acc[mt][nt][2] = b0; acc[mt][nt][3] = b1;
        }
    }

    const int arow = mw * 32 + (l & 15);
    const int acol = (l >> 4) << 3;
    const int brow = nh * 32 + ((l >> 4) << 3) + (l & 7);
    const int bcol = ((l >> 3) & 1) << 3;

    uint4 ld[6];
    int lrow[6], lseg[6], lisA[6];
#pragma unroll
    for (int q = 0; q < 6; q++) {
        int cid = q * 256 + tid;
        lisA[q] = (cid < 1024);
        int c2 = lisA[q] ? cid : cid - 1024;
        lrow[q] = c2 >> 3;
        lseg[q] = c2 & 7;
    }

#define LOAD_TILE(kc) do { \
    _Pragma("unroll") \
    for (int q = 0; q < 6; q++) { \
        if (lisA[q]) { \
            int orig = sRow[lrow[q]]; \
            const __half* src = ((kc) < 8) \
                ? (g_hh  + (size_t)orig * CH + (kc) * 64 + lseg[q] * 8) \
                : (g_h1h + (size_t)orig * CH + ((kc) - 8) * 64 + lseg[q] * 8); \
            ld[q] = *(const uint4*)src; \
        } else { \
            ld[q] = *(const uint4*)(g_wWh + (size_t)(n0 + lrow[q]) * KK + (kc) * 64 + lseg[q] * 8); \
        } \
    } \
} while (0)

    LOAD_TILE(0);

#pragma unroll 1
    for (int kc = 0; kc < 16; kc++) {
        __syncthreads();
#pragma unroll
        for (int q = 0; q < 6; q++) {
            if (lisA[q]) *(uint4*)&sA[lrow[q]][lseg[q] * 8] = ld[q];
            else         *(uint4*)&sB[lrow[q]][lseg[q] * 8] = ld[q];
        }
        __syncthreads();
        if (kc < 15) LOAD_TILE(kc + 1);

#pragma unroll
        for (int ks = 0; ks < 4; ks++) {
            uint32_t Af[2][4];
            LDSM_X4(Af[0], smem_u32(&sA[arow][ks * 16 + acol]));
            LDSM_X4(Af[1], smem_u32(&sA[arow + 16][ks * 16 + acol]));
            uint32_t Bf0[4], Bf1[4];
            LDSM_X4(Bf0, smem_u32(&sB[brow][ks * 16 + bcol]));
            LDSM_X4(Bf1, smem_u32(&sB[brow + 16][ks * 16 + bcol]));
#pragma unroll
            for (int mt = 0; mt < 2; mt++) {
                mma_f16(acc[mt][0], Af[mt][0], Af[mt][1], Af[mt][2], Af[mt][3], Bf0[0], Bf0[1]);
                mma_f16(acc[mt][1], Af[mt][0], Af[mt][1], Af[mt][2], Af[mt][3], Bf0[2], Bf0[3]);
                mma_f16(acc[mt][2], Af[mt][0], Af[mt][1], Af[mt][2], Af[mt][3], Bf1[0], Bf1[1]);
                mma_f16(acc[mt][3], Af[mt][0], Af[mt][1], Af[mt][2], Af[mt][3], Bf1[2], Bf1[3]);
            }
        }
    }

    // epilogue: selu + node mask + residual, rows gathered via sRow
#pragma unroll
    for (int mt = 0; mt < 2; mt++) {
        const int ms = mw * 32 + mt * 16 + gid;       // slot in tile
        const int r0 = sRow[ms];
        const int r1 = sRow[ms + 8];
        const float nm0 = __ldg(nmask + r0);
        const float nm1 = __ldg(nmask + r1);
#pragma unroll
        for (int nt = 0; nt < 4; nt++) {
            int n = n0 + nh * 32 + nt * 8 + tig * 2;
            float2 hr0 = *(const float2*)(h + (size_t)r0 * CH + n);
            float2 hr1 = *(const float2*)(h + (size_t)r1 * CH + n);
            float2 o0, o1;
            o0.x = selu_f(acc[mt][nt][0]) * nm0 + hr0.x;
            o0.y = selu_f(acc[mt][nt][1]) * nm0 + hr0.y;
            o1.x = selu_f(acc[mt][nt][2]) * nm1 + hr1.x;
            o1.y = selu_f(acc[mt][nt][3]) * nm1 + hr1.y;
            *(float2*)(out + (size_t)r0 * CH + n) = o0;
            *(float2*)(out + (size_t)r1 * CH + n) = o1;
        }
    }
}

// =====================================================================
extern "C" void kernel_launch(void* const* d_in, const int* in_sizes, int n_in,
                              void* d_out, int out_size) {
    (void)in_sizes; (void)n_in; (void)out_size;
    const float* h     = (const float*)d_in[0];
    const float* e     = (const float*)d_in[1];
    const float* nmask = (const float*)d_in[2];
    const float* emask = (const float*)d_in[3];
    const float* fW    = (const float*)d_in[4];
    const float* fb    = (const float*)d_in[5];
    const float* wW    = (const float*)d_in[6];
    const float* wb    = (const float*)d_in[7];
    float* out = (float*)d_out;

    prep_kernel<<<512, 256>>>(fW, wW, h, nmask);
    edge_mma_kernel<<<NB * 32, 512>>>(e, emask, nmask, fb);
    node_mma_kernel<<<dim3(CH / 64, (NB * NA) / 128), 256>>>(h, nmask, wb, out);
}

// round 7
// speedup vs baseline: 6.3031x; 1.2826x over previous
#include <cuda_runtime.h>
#include <cuda_fp16.h>
#include <cstdint>

#define NB 16
#define NA 128
#define CH 512
#define EF 30
#define KK 1024   // 2*CH

// device scratch (allocation-free, zero-initialized at load)
__device__ __half   g_h1h[(size_t)NB * NA * CH];    // h1 result, fp16 (masked rows stay 0)
__device__ __half   g_hh [(size_t)NB * NA * CH];    // h as fp16 (MMA operand)
__device__ __half   g_wWh[(size_t)CH * KK];         // w_W as fp16
__device__ uint32_t g_afrag[16 * 2 * 2 * 32 * 4];   // fW A-fragments
__device__ int      g_Mact;                         // # active node rows
__device__ int      g_rowidx[NB * NA];              // active rows first, then masked

__device__ __forceinline__ float selu_f(float x) {
    const float sc  = 1.0507009873554805f;
    const float sca = 1.7580993408473766f;  // scale*alpha
    float ex  = __expf(x);
    float neg = fmaf(ex, sca, -sca);
    float pos = sc * x;
    return (x > 0.0f) ? pos : neg;
}

__device__ __forceinline__ uint32_t smem_u32(const void* p) {
    uint32_t a;
    asm("{ .reg .u64 t; cvta.to.shared.u64 t, %1; cvt.u32.u64 %0, t; }" : "=r"(a) : "l"(p));
    return a;
}

#define LDSM_X4(r, addr) \
    asm volatile("ldmatrix.sync.aligned.m8n8.x4.shared.b16 {%0,%1,%2,%3}, [%4];" \
        : "=r"((r)[0]), "=r"((r)[1]), "=r"((r)[2]), "=r"((r)[3]) : "r"(addr))

__device__ __forceinline__ void mma_f16(float* d, uint32_t a0, uint32_t a1,
                                        uint32_t a2, uint32_t a3,
                                        uint32_t b0, uint32_t b1) {
    asm volatile(
        "mma.sync.aligned.m16n8k16.row.col.f32.f16.f16.f32 "
        "{%0,%1,%2,%3}, {%4,%5,%6,%7}, {%8,%9}, {%0,%1,%2,%3};"
        : "+f"(d[0]), "+f"(d[1]), "+f"(d[2]), "+f"(d[3])
        : "r"(a0), "r"(a1), "r"(a2), "r"(a3), "r"(b0), "r"(b1));
}

// =====================================================================
// Prep: block 0 = parallel row-compaction scan; blocks 1..N = fp16
// conversions + fW fragments.
// =====================================================================
__global__ void __launch_bounds__(256)
prep_kernel(const float* __restrict__ fW, const float* __restrict__ wW,
            const float* __restrict__ h, const float* __restrict__ nmask) {
    if (blockIdx.x == 0) {
        // parallel stable partition of 2048 rows (active first)
        __shared__ int wsum[8];
        __shared__ int totalS;
        const int tt = threadIdx.x;
        const int l  = tt & 31;
        const int wg = tt >> 5;
        bool p[8];
        int local = 0;
#pragma unroll
        for (int q = 0; q < 8; q++) {
            p[q] = nmask[tt * 8 + q] > 0.5f;
            local += p[q];
        }
        // inclusive warp scan of per-thread counts
        int inc = local;
#pragma unroll
        for (int d = 1; d < 32; d <<= 1) {
            int v = __shfl_up_sync(0xffffffffu, inc, d);
            if (l >= d) inc += v;
        }
        if (l == 31) wsum[wg] = inc;
        __syncthreads();
        if (tt == 0) {
            int s = 0;
#pragma unroll
            for (int i = 0; i < 8; i++) { int c = wsum[i]; wsum[i] = s; s += c; }
            totalS = s;
            g_Mact = s;
        }
        __syncthreads();
        int aoff = wsum[wg] + inc - local;   // exclusive prefix for this thread
        int moff = tt * 8 - aoff;
        const int M = totalS;
#pragma unroll
        for (int q = 0; q < 8; q++) {
            int r = tt * 8 + q;
            if (p[q]) g_rowidx[aoff++] = r;
            else      g_rowidx[M + moff++] = r;
        }
        return;
    }

    const int t = (blockIdx.x - 1) * 256 + threadIdx.x;
    const int stride = (gridDim.x - 1) * 256;

    for (int i = t; i < (NB * NA * CH) / 4; i += stride) {
        float4 f = ((const float4*)h)[i];
        ((__half2*)g_hh)[i * 2]     = __floats2half2_rn(f.x, f.y);
        ((__half2*)g_hh)[i * 2 + 1] = __floats2half2_rn(f.z, f.w);
    }
    for (int i = t; i < (CH * KK) / 4; i += stride) {
        float4 f = ((const float4*)wW)[i];
        ((__half2*)g_wWh)[i * 2]     = __floats2half2_rn(f.x, f.y);
        ((__half2*)g_wWh)[i * 2 + 1] = __floats2half2_rn(f.z, f.w);
    }
    for (int idx = t; idx < 8192; idx += stride) {
        int r  = idx & 3;
        int l  = (idx >> 2) & 31;
        int ks = (idx >> 7) & 1;
        int mt = (idx >> 8) & 1;
        int cc = idx >> 9;
        int row = cc * 32 + mt * 16 + (r & 1) * 8 + (l >> 2);
        int k   = ks * 16 + (r >> 1) * 8 + (l & 3) * 2;
        float v0 = (k     < EF) ? fW[row * EF + k]     : 0.0f;
        float v1 = (k + 1 < EF) ? fW[row * EF + k + 1] : 0.0f;
        __half2 hv = __floats2half2_rn(v0, v1);
        g_afrag[idx] = *(uint32_t*)&hv;
    }
}

// =====================================================================
// Edge kernel: one CTA per 4 COMPACTED ACTIVE rows (from g_rowidx).
// j compacted per row by edge_mask (warp ballot). Balanced load.
// =====================================================================
#define EROWB 80

__global__ void __launch_bounds__(512, 2)
edge_mma_kernel(const float* __restrict__ e,
                const float* __restrict__ emask,
                const float* __restrict__ fb) {
    __shared__ __align__(16) char sE[4 * NA * EROWB];   // 40960 B
    __shared__ int   sJ[4][NA];
    __shared__ float sEm[4][NA];
    __shared__ int   sNj[4];
    __shared__ int   sRowA[4];
    __shared__ int   sWc[4][4];

    const int tid = threadIdx.x;
    const int i0  = blockIdx.x * 4;       // index into compacted active list
    const int Mact = g_Mact;
    if (i0 >= Mact) return;

    // zero staging (pad rows/slots must be 0)
    {
        uint4 z = make_uint4(0, 0, 0, 0);
        uint4* p = (uint4*)sE;
        for (int i = tid; i < (4 * NA * EROWB) / 16; i += 512) p[i] = z;
        sJ[tid >> 7][tid & 127]  = 0;
        sEm[tid >> 7][tid & 127] = 0.0f;
    }
    if (tid < 4) sRowA[tid] = (i0 + tid < Mact) ? g_rowidx[i0 + tid] : -1;
    __syncthreads();

    // ---- j compaction per group g (handles active row sRowA[g]) ----
    const int g  = tid >> 7;
    const int t  = tid & 127;
    const int wg = (tid >> 5) & 3;
    const int l  = tid & 31;
    {
        const int row = sRowA[g];
        bool pred = false;
        if (row >= 0) pred = emask[(size_t)row * NA + t] > 0.5f;
        unsigned bal = __ballot_sync(0xffffffffu, pred);
        int pos = __popc(bal & ((1u << l) - 1u));
        if (l == 0) sWc[g][wg] = __popc(bal);
        __syncthreads();
        int off = 0;
#pragma unroll
        for (int k = 0; k < 3; k++) if (k < wg) off += sWc[g][k];
        if (pred) {
            int s = off + pos;
            sJ[g][s]  = t;
            sEm[g][s] = 1.0f;
        }
        if (t == 0) sNj[g] = sWc[g][0] + sWc[g][1] + sWc[g][2] + sWc[g][3];
    }
    __syncthreads();

    // ---- stage e rows (compacted j) as fp16 ----
    for (int idx = tid; idx < 4 * NA * EF; idx += 512) {
        int gg  = idx / (NA * EF);
        int rem = idx - gg * (NA * EF);
        int s   = rem / EF;
        int c   = rem - s * EF;
        const int row = sRowA[gg];
        if (row < 0 || s >= sNj[gg]) continue;
        int j = sJ[gg][s];
        float v = e[(size_t)row * (NA * EF) + j * EF + c];
        *(__half*)(sE + gg * (NA * EROWB) + s * EROWB + c * 2) = __float2half_rn(v);
    }
    __syncthreads();

    const int w     = tid >> 5;
    const int gid   = l >> 2;
    const int tig   = l & 3;
    const int cbase = w * 32;
    const int brow_off = ((l >> 4) << 3) + (l & 7);
    const int bkk_off  = ((l >> 3) & 1) << 3;

    uint4 AH[2][2];
#pragma unroll
    for (int mt = 0; mt < 2; mt++)
#pragma unroll
        for (int ks = 0; ks < 2; ks++)
            AH[mt][ks] = *(const uint4*)&g_afrag[(((w * 2 + mt) * 2 + ks) * 32 + l) * 4];

    float bias0[2], bias1[2];
#pragma unroll
    for (int mt = 0; mt < 2; mt++) {
        bias0[mt] = __ldg(fb + cbase + 16 * mt + gid);
        bias1[mt] = __ldg(fb + cbase + 16 * mt + gid + 8);
    }

    const uint32_t sbE = smem_u32(sE);

#pragma unroll 1
    for (int ii = 0; ii < 4; ii++) {
        const int row = sRowA[ii];
        if (row < 0) continue;
        const __half* hb = g_hh + (size_t)(row >> 7) * (NA * CH);   // b = row/128
        const int nsc = (sNj[ii] + 15) >> 4;
        float ps[4] = {0.f, 0.f, 0.f, 0.f};
        const uint32_t ebase = sbE + ii * (NA * EROWB);

#pragma unroll 1
        for (int sc = 0; sc < nsc; sc++) {
            const int j0 = sc * 16;
            uint32_t BH0[4], BH1[4];
            uint32_t jr = ebase + (uint32_t)(j0 + brow_off) * EROWB + bkk_off * 2;
            LDSM_X4(BH0, jr);        // k 0..15
            LDSM_X4(BH1, jr + 32);   // k 16..31

            int jsA[2], jsB[2];
            float em0[2], em1[2];
#pragma unroll
            for (int nt = 0; nt < 2; nt++) {
                const int slot = j0 + 8 * nt + 2 * tig;
                jsA[nt] = sJ[ii][slot];
                jsB[nt] = sJ[ii][slot + 1];
                em0[nt] = sEm[ii][slot];
                em1[nt] = sEm[ii][slot + 1];
            }
            float hv[2][2][4];
#pragma unroll
            for (int nt = 0; nt < 2; nt++)
#pragma unroll
                for (int mt = 0; mt < 2; mt++) {
                    const int c0 = cbase + 16 * mt + gid;
                    hv[nt][mt][0] = __half2float(__ldg(hb + (size_t)jsA[nt] * CH + c0));
                    hv[nt][mt][1] = __half2float(__ldg(hb + (size_t)jsB[nt] * CH + c0));
                    hv[nt][mt][2] = __half2float(__ldg(hb + (size_t)jsA[nt] * CH + c0 + 8));
                    hv[nt][mt][3] = __half2float(__ldg(hb + (size_t)jsB[nt] * CH + c0 + 8));
                }

            float acc[2][2][4];
#pragma unroll
            for (int mt = 0; mt < 2; mt++)
#pragma unroll
                for (int nt = 0; nt < 2; nt++) {
                    acc[mt][nt][0] = bias0[mt];
                    acc[mt][nt][1] = bias0[mt];
                    acc[mt][nt][2] = bias1[mt];
                    acc[mt][nt][3] = bias1[mt];
                }

#pragma unroll
            for (int mt = 0; mt < 2; mt++)
#pragma unroll
                for (int nt = 0; nt < 2; nt++) {
                    float* d = acc[mt][nt];
                    mma_f16(d, AH[mt][0].x, AH[mt][0].y, AH[mt][0].z, AH[mt][0].w,
                            BH0[nt * 2], BH0[nt * 2 + 1]);
                    mma_f16(d, AH[mt][1].x, AH[mt][1].y, AH[mt][1].z, AH[mt][1].w,
                            BH1[nt * 2], BH1[nt * 2 + 1]);
                }

#pragma unroll
            for (int nt = 0; nt < 2; nt++)
#pragma unroll
                for (int mt = 0; mt < 2; mt++) {
                    float s0 = selu_f(acc[mt][nt][0]) * em0[nt];
                    float s1 = selu_f(acc[mt][nt][1]) * em1[nt];
                    float s2 = selu_f(acc[mt][nt][2]) * em0[nt];
                    float s3 = selu_f(acc[mt][nt][3]) * em1[nt];
                    ps[mt * 2]     = fmaf(s0, hv[nt][mt][0], fmaf(s1, hv[nt][mt][1], ps[mt * 2]));
                    ps[mt * 2 + 1] = fmaf(s2, hv[nt][mt][2], fmaf(s3, hv[nt][mt][3], ps[mt * 2 + 1]));
                }
        }

#pragma unroll
        for (int i = 0; i < 4; i++) {
            ps[i] += __shfl_xor_sync(0xffffffffu, ps[i], 1);
            ps[i] += __shfl_xor_sync(0xffffffffu, ps[i], 2);
        }
        if (tig == 0) {
            __half* o = g_h1h + (size_t)row * CH;
#pragma unroll
            for (int mt = 0; mt < 2; mt++) {
                o[cbase + 16 * mt + gid]     = __float2half_rn(ps[mt * 2]);
                o[cbase + 16 * mt + gid + 8] = __float2half_rn(ps[mt * 2 + 1]);
            }
        }
    }
}

// =====================================================================
// Node MLP: 64x64 tiles over compacted rows -> ~2x more CTAs, better
// SMSP spread. Fully-masked tiles degrade to out=h copy.
// =====================================================================
#define NROWH 72

__global__ void __launch_bounds__(256)
node_mma_kernel(const float* __restrict__ h,
                const float* __restrict__ nmask,
                const float* __restrict__ wb,
                float* __restrict__ out) {
    __shared__ __align__(16) __half sA[64][NROWH];
    __shared__ __align__(16) __half sB[64][NROWH];
    __shared__ int sRow[64];

    const int n0  = blockIdx.x * 64;
    const int m0  = blockIdx.y * 64;
    const int tid = threadIdx.x;

    if (tid < 64) sRow[tid] = g_rowidx[m0 + tid];
    __syncthreads();

    const int Mact = g_Mact;
    if (m0 >= Mact) {
        if (n0 == 0) {
            for (int idx = tid; idx < 64 * 128; idx += 256) {
                int r = idx >> 7, c4 = idx & 127;
                int orig = sRow[r];
                ((float4*)(out + (size_t)orig * CH))[c4] =
                    ((const float4*)(h + (size_t)orig * CH))[c4];
            }
        }
        return;
    }

    const int w   = tid >> 5;
    const int l   = tid & 31;
    const int gid = l >> 2;
    const int tig = l & 3;
    const int mw  = w >> 1;   // 0..3: 16 m-rows per warp
    const int nh  = w & 1;    // 0..1: 32 n-cols per warp

    float acc[4][4];
#pragma unroll
    for (int nt = 0; nt < 4; nt++) {
        int n = n0 + nh * 32 + nt * 8 + tig * 2;
        float b0 = __ldg(wb + n), b1 = __ldg(wb + n + 1);
        acc[nt][0] = b0; acc[nt][1] = b1;
        acc[nt][2] = b0; acc[nt][3] = b1;
    }

    const int arow = mw * 16 + (l & 15);
    const int acol = (l >> 4) << 3;
    const int brow = nh * 32 + ((l >> 4) << 3) + (l & 7);
    const int bcol = ((l >> 3) & 1) << 3;

    uint4 ld[4];
    int lrow[4], lseg[4], lisA[4];
#pragma unroll
    for (int q = 0; q < 4; q++) {
        int cid = q * 256 + tid;          // 0..1023
        lisA[q] = (cid < 512);
        int c2 = cid & 511;
        lrow[q] = c2 >> 3;
        lseg[q] = c2 & 7;
    }

#define LOAD_TILE(kc) do { \
    _Pragma("unroll") \
    for (int q = 0; q < 4; q++) { \
        if (lisA[q]) { \
            int orig = sRow[lrow[q]]; \
            const __half* src = ((kc) < 8) \
                ? (g_hh  + (size_t)orig * CH + (kc) * 64 + lseg[q] * 8) \
                : (g_h1h + (size_t)orig * CH + ((kc) - 8) * 64 + lseg[q] * 8); \
            ld[q] = *(const uint4*)src; \
        } else { \
            ld[q] = *(const uint4*)(g_wWh + (size_t)(n0 + lrow[q]) * KK + (kc) * 64 + lseg[q] * 8); \
        } \
    } \
} while (0)

    LOAD_TILE(0);

#pragma unroll 1
    for (int kc = 0; kc < 16; kc++) {
        __syncthreads();
#pragma unroll
        for (int q = 0; q < 4; q++) {
            if (lisA[q]) *(uint4*)&sA[lrow[q]][lseg[q] * 8] = ld[q];
            else         *(uint4*)&sB[lrow[q]][lseg[q] * 8] = ld[q];
        }
        __syncthreads();
        if (kc < 15) LOAD_TILE(kc + 1);

#pragma unroll
        for (int ks = 0; ks < 4; ks++) {
            uint32_t Af[4];
            LDSM_X4(Af, smem_u32(&sA[arow][ks * 16 + acol]));
            uint32_t Bf0[4], Bf1[4];
            LDSM_X4(Bf0, smem_u32(&sB[brow][ks * 16 + bcol]));
            LDSM_X4(Bf1, smem_u32(&sB[brow + 16][ks * 16 + bcol]));
            mma_f16(acc[0], Af[0], Af[1], Af[2], Af[3], Bf0[0], Bf0[1]);
            mma_f16(acc[1], Af[0], Af[1], Af[2], Af[3], Bf0[2], Bf0[3]);
            mma_f16(acc[2], Af[0], Af[1], Af[2], Af[3], Bf1[0], Bf1[1]);
            mma_f16(acc[3], Af[0], Af[1], Af[2], Af[3], Bf1[2], Bf1[3]);
        }
    }

    // epilogue: selu + node mask + residual (gathered rows)
    const int ms = mw * 16 + gid;
    const int r0 = sRow[ms];
    const int r1 = sRow[ms + 8];
    const float nm0 = __ldg(nmask + r0);
    const float nm1 = __ldg(nmask + r1);
#pragma unroll
    for (int nt = 0; nt < 4; nt++) {
        int n = n0 + nh * 32 + nt * 8 + tig * 2;
        float2 hr0 = *(const float2*)(h + (size_t)r0 * CH + n);
        float2 hr1 = *(const float2*)(h + (size_t)r1 * CH + n);
        float2 o0, o1;
        o0.x = selu_f(acc[nt][0]) * nm0 + hr0.x;
        o0.y = selu_f(acc[nt][1]) * nm0 + hr0.y;
        o1.x = selu_f(acc[nt][2]) * nm1 + hr1.x;
        o1.y = selu_f(acc[nt][3]) * nm1 + hr1.y;
        *(float2*)(out + (size_t)r0 * CH + n) = o0;
        *(float2*)(out + (size_t)r1 * CH + n) = o1;
    }
}

// =====================================================================
extern "C" void kernel_launch(void* const* d_in, const int* in_sizes, int n_in,
                              void* d_out, int out_size) {
    (void)in_sizes; (void)n_in; (void)out_size;
    const float* h     = (const float*)d_in[0];
    const float* e     = (const float*)d_in[1];
    const float* nmask = (const float*)d_in[2];
    const float* emask = (const float*)d_in[3];
    const float* fW    = (const float*)d_in[4];
    const float* fb    = (const float*)d_in[5];
    const float* wW    = (const float*)d_in[6];
    const float* wb    = (const float*)d_in[7];
    float* out = (float*)d_out;

    prep_kernel<<<513, 256>>>(fW, wW, h, nmask);
    edge_mma_kernel<<<(NB * NA + 3) / 4, 512>>>(e, emask, fb);
    node_mma_kernel<<<dim3(CH / 64, (NB * NA) / 64), 256>>>(h, nmask, wb, out);
}